// round 11
// baseline (speedup 1.0000x reference)
#include <cuda_runtime.h>
#include <cuda_bf16.h>

#define B_      4
#define CIN     256
#define HH      32
#define WW      88
#define HW      2816
#define PTOT    11264
#define COUT    128
#define OUTH    432
#define OUTW    496
#define XVEC    124             // 496/4
#define NPLANE  512
#define YTILE   54              // 432 = 8*54
#define NYT     8
#define SROWS   6
#define YHALF   27

#define KC      32              // GEMM k-chunk
#define PB      64              // positions per block
#define CB      64              // channels per block

__device__ float g_ctx[NPLANE * HW];

// ---------------------------------------------------------------------------
// packed f32x2 helpers
// ---------------------------------------------------------------------------
__device__ __forceinline__ unsigned long long pk2(float x) {
    unsigned long long r;
    asm("mov.b64 %0, {%1, %1};" : "=l"(r) : "f"(x));
    return r;
}
__device__ __forceinline__ void ffma2(unsigned long long& d,
                                      unsigned long long a,
                                      unsigned long long b) {
    asm("fma.rn.f32x2 %0, %1, %2, %0;" : "+l"(d) : "l"(a), "l"(b));
}
__device__ __forceinline__ float2 upk(unsigned long long v) {
    float2 r;
    asm("mov.b64 {%0, %1}, %2;" : "=f"(r.x), "=f"(r.y) : "l"(v));
    return r;
}

// ---------------------------------------------------------------------------
// Kernel 1: GEMM (R8 mainloop, in-block W transpose -> no prep kernel).
// Block 64c x 64p, 128 threads, thread tile 4 channel-pairs x 4 positions,
// FFMA2 inner loop, KC=32 double-buffered.
// W loader: each thread LDGs float4 along k of one c-row of Wc, stores with
// 4 scalar STS into Ws[k][c] (lane-distinct c -> conflict-free).
// 1/64 scaling applied in the epilogue.
// ---------------------------------------------------------------------------
__global__ __launch_bounds__(128)
void lss_gemm_kernel(const float* __restrict__ feat,
                     const float* __restrict__ Wc,
                     const float* __restrict__ bc)
{
    __shared__ float Ws[2][KC * CB];   // [k][c] 16KB
    __shared__ float Fs[2][KC * PB];   // [k][p] 16KB

    const int tid   = threadIdx.x;
    const int p0    = blockIdx.x * PB;
    const int b     = p0 / HW;
    const int hw0   = p0 - b * HW;
    const int cbase = blockIdx.y * CB;          // 0 or 64

    const float4* feat4 = (const float4*)(feat + (size_t)b * CIN * HW + hw0); // row stride 704 f4

    // F loader mapping (R8 proven)
    const int lkk = tid >> 4;        // 0..7
    const int lcv = tid & 15;        // 0..15

    // W loader mapping: c = tid&63, kv-quad base = (tid>>6)*4
    const int lc  = tid & 63;
    const int lkv = (tid >> 6) << 2;                 // 0 or 4
    const float4* Wrow = (const float4*)(Wc + (size_t)(64 + cbase + lc) * CIN);

    float4 wreg[4], freg[4];

    // prologue: chunk 0
#pragma unroll
    for (int it = 0; it < 4; it++) {
        wreg[it] = Wrow[lkv + it];                       // k float4 idx 0..7
        freg[it] = feat4[(size_t)(lkk + it * 8) * 704 + lcv];
    }
#pragma unroll
    for (int it = 0; it < 4; it++) {
        int kv = lkv + it;
        Ws[0][(kv * 4 + 0) * CB + lc] = wreg[it].x;
        Ws[0][(kv * 4 + 1) * CB + lc] = wreg[it].y;
        Ws[0][(kv * 4 + 2) * CB + lc] = wreg[it].z;
        Ws[0][(kv * 4 + 3) * CB + lc] = wreg[it].w;
        ((float4*)Fs[0])[(lkk + it * 8) * 16 + lcv] = freg[it];
    }
    __syncthreads();

    const int cy = (tid >> 4) << 3;   // channel base 0..56 (4 pairs)
    const int px = (tid & 15) << 2;   // position base 0..60

    unsigned long long acc[4][4];     // [cpair][pos]
#pragma unroll
    for (int i = 0; i < 4; i++)
#pragma unroll
        for (int j = 0; j < 4; j++) acc[i][j] = 0ull;

    int buf = 0;
    for (int ch = 0; ch < CIN / KC; ch++) {
        if (ch < CIN / KC - 1) {
            int kq0 = (ch + 1) * 8;   // float4-k base of next chunk
#pragma unroll
            for (int it = 0; it < 4; it++) {
                wreg[it] = Wrow[kq0 + lkv + it];
                freg[it] = feat4[(size_t)((ch + 1) * KC + lkk + it * 8) * 704 + lcv];
            }
        }

        const float* Wsb = Ws[buf] + cy;
        const float* Fsb = Fs[buf] + px;
#pragma unroll 16
        for (int k = 0; k < KC; k++) {
            ulonglong2 w01 = *(const ulonglong2*)(Wsb + k * CB);       // pairs (c0,c1),(c2,c3)
            ulonglong2 w23 = *(const ulonglong2*)(Wsb + k * CB + 4);   // pairs (c4,c5),(c6,c7)
            float4 f = *(const float4*)(Fsb + k * PB);
            unsigned long long f0 = pk2(f.x), f1 = pk2(f.y),
                               f2 = pk2(f.z), f3 = pk2(f.w);
            ffma2(acc[0][0], w01.x, f0); ffma2(acc[0][1], w01.x, f1);
            ffma2(acc[0][2], w01.x, f2); ffma2(acc[0][3], w01.x, f3);
            ffma2(acc[1][0], w01.y, f0); ffma2(acc[1][1], w01.y, f1);
            ffma2(acc[1][2], w01.y, f2); ffma2(acc[1][3], w01.y, f3);
            ffma2(acc[2][0], w23.x, f0); ffma2(acc[2][1], w23.x, f1);
            ffma2(acc[2][2], w23.x, f2); ffma2(acc[2][3], w23.x, f3);
            ffma2(acc[3][0], w23.y, f0); ffma2(acc[3][1], w23.y, f1);
            ffma2(acc[3][2], w23.y, f2); ffma2(acc[3][3], w23.y, f3);
        }

        if (ch < CIN / KC - 1) {
            int nb = buf ^ 1;
#pragma unroll
            for (int it = 0; it < 4; it++) {
                int kv = lkv + it;
                Ws[nb][(kv * 4 + 0) * CB + lc] = wreg[it].x;
                Ws[nb][(kv * 4 + 1) * CB + lc] = wreg[it].y;
                Ws[nb][(kv * 4 + 2) * CB + lc] = wreg[it].z;
                Ws[nb][(kv * 4 + 3) * CB + lc] = wreg[it].w;
                ((float4*)Fs[nb])[(lkk + it * 8) * 16 + lcv] = freg[it];
            }
            __syncthreads();
            buf = nb;
        }
    }

    const float inv64 = 1.0f / 64.0f;
#pragma unroll
    for (int j = 0; j < 4; j++) {
        int c0 = cbase + cy + 2 * j;
        float b0 = bc[64 + c0] * inv64;
        float b1 = bc[64 + c0 + 1] * inv64;
        float2 v0 = upk(acc[j][0]), v1 = upk(acc[j][1]),
               v2 = upk(acc[j][2]), v3 = upk(acc[j][3]);
        float4 r0 = make_float4(fmaf(v0.x, inv64, b0), fmaf(v1.x, inv64, b0),
                                fmaf(v2.x, inv64, b0), fmaf(v3.x, inv64, b0));
        float4 r1 = make_float4(fmaf(v0.y, inv64, b1), fmaf(v1.y, inv64, b1),
                                fmaf(v2.y, inv64, b1), fmaf(v3.y, inv64, b1));
        *(float4*)&g_ctx[((size_t)(b * COUT + c0)) * HW + hw0 + px]     = r0;
        *(float4*)&g_ctx[((size_t)(b * COUT + c0 + 1)) * HW + hw0 + px] = r1;
    }
}

// ---------------------------------------------------------------------------
// Kernel 2: separable bilinear upsample (R7/R8 proven version, unchanged).
// ---------------------------------------------------------------------------
__global__ __launch_bounds__(256)
void lss_upsample_kernel(float* __restrict__ out)
{
    __shared__ float raw[SROWS][WW];
    __shared__ float hrow[SROWS][OUTW];
    __shared__ float ywy[YTILE];
    __shared__ int   yi0s[YTILE];

    const int tid   = threadIdx.x;
    const int t     = blockIdx.x;      // 0..7
    const int plane = blockIdx.y;      // 0..511

    const float SY = 32.0f / 432.0f;
    const float OY = 16.0f / 432.0f - 0.5f;
    const float SX = 88.0f / 496.0f;
    const float OX = 44.0f / 496.0f - 0.5f;

    const int rbase = max(4 * t - 1, 0);

    if (tid < YTILE) {
        int Y = t * YTILE + tid;
        float fy = fminf(fmaxf((float)Y * SY + OY, 0.0f), 31.0f);
        int   y0 = (int)fy;
        ywy[tid]  = fy - (float)y0;
        yi0s[tid] = y0 - rbase;        // 0..4, monotone non-decreasing
    }

    // Phase A: load 6 source rows (edge-clamped)
    const float* cb = g_ctx + (size_t)plane * HW;
    for (int i = tid; i < SROWS * WW; i += 256) {
        int r = i / WW, x = i - r * WW;
        int ry = min(rbase + r, HH - 1);
        raw[r][x] = cb[ry * WW + x];
    }
    __syncthreads();

    // Phase B: horizontal interpolation
    for (int i = tid; i < SROWS * 512; i += 256) {
        int r = i >> 9, X = i & 511;
        if (X < OUTW) {
            float fx = fminf(fmaxf((float)X * SX + OX, 0.0f), 87.0f);
            int   x0 = (int)fx;
            float wx = fx - (float)x0;
            int   x1 = min(x0 + 1, WW - 1);
            float a = raw[r][x0];
            hrow[r][X] = fmaf(wx, raw[r][x1] - a, a);
        }
    }
    __syncthreads();

    // Phase C: vertical pass. Two 124-thread halves each cover 27 rows.
    const int half = tid >> 7;         // 0 or 1
    const int lx   = tid & 127;        // x-column within half
    if (lx < XVEC) {
        const int xo    = lx << 2;
        const int ybeg  = half * YHALF;
        const int yend  = ybeg + YHALF;
        float4* orow = (float4*)out + (size_t)plane * OUTH * XVEC
                       + (size_t)(t * YTILE + ybeg) * XVEC + lx;
        int yy = ybeg;
        const int r0 = yi0s[ybeg];
#pragma unroll
        for (int r = 0; r < 5; r++) {
            if (r >= r0 && yy < yend && yi0s[yy] == r) {
                float4 a = *(const float4*)&hrow[r][xo];
                float4 b = *(const float4*)&hrow[r + 1][xo];
                float4 d;
                d.x = b.x - a.x; d.y = b.y - a.y; d.z = b.z - a.z; d.w = b.w - a.w;
                do {
                    float wy = ywy[yy];
                    float4 o;
                    o.x = fmaf(wy, d.x, a.x);
                    o.y = fmaf(wy, d.y, a.y);
                    o.z = fmaf(wy, d.z, a.z);
                    o.w = fmaf(wy, d.w, a.w);
                    __stcs(orow, o);
                    orow += XVEC;
                    yy++;
                } while (yy < yend && yi0s[yy] == r);
            }
        }
    }
}

extern "C" void kernel_launch(void* const* d_in, const int* in_sizes, int n_in,
                              void* d_out, int out_size)
{
    const float* feat = (const float*)d_in[0];
    const float* Wc   = (const float*)d_in[1];
    const float* bc   = (const float*)d_in[2];
    float* out        = (float*)d_out;

    dim3 ggrid(PTOT / PB, 2);
    lss_gemm_kernel<<<ggrid, 128>>>(feat, Wc, bc);

    dim3 ugrid(NYT, NPLANE);
    lss_upsample_kernel<<<ugrid, 256>>>(out);
}

// round 12
// speedup vs baseline: 1.5107x; 1.5107x over previous
#include <cuda_runtime.h>
#include <cuda_bf16.h>

#define B_      4
#define CIN     256
#define HH      32
#define WW      88
#define HW      2816
#define PTOT    11264
#define COUT    128
#define OUTH    432
#define OUTW    496
#define XVEC    124             // 496/4
#define NPLANE  512
#define YTILE   54              // 432 = 8*54
#define NYT     8
#define SROWS   6
#define YHALF   27

#define KC      32              // GEMM k-chunk
#define PB      64              // positions per block
#define CB      64              // channels per block
#define KSPL    128             // k per in-block split

__device__ float g_ctx[NPLANE * HW];
__device__ float g_WcT[CIN * COUT];   // [k][c], pre-scaled by 1/64

// ---------------------------------------------------------------------------
// packed f32x2 helpers
// ---------------------------------------------------------------------------
__device__ __forceinline__ unsigned long long pk2(float x) {
    unsigned long long r;
    asm("mov.b64 %0, {%1, %1};" : "=l"(r) : "f"(x));
    return r;
}
__device__ __forceinline__ void ffma2(unsigned long long& d,
                                      unsigned long long a,
                                      unsigned long long b) {
    asm("fma.rn.f32x2 %0, %1, %2, %0;" : "+l"(d) : "l"(a), "l"(b));
}
__device__ __forceinline__ float2 upk(unsigned long long v) {
    float2 r;
    asm("mov.b64 {%0, %1}, %2;" : "=f"(r.x), "=f"(r.y) : "l"(v));
    return r;
}

// ---------------------------------------------------------------------------
// Kernel 0: coalesced tile-transpose prep: WcT[k][c] = Wc[64+c][k] / 64
// ---------------------------------------------------------------------------
__global__ __launch_bounds__(256)
void lss_prep_kernel(const float* __restrict__ Wc)
{
    __shared__ float s[32][33];
    const int tx = threadIdx.x & 31;
    const int ty = threadIdx.x >> 5;      // 0..7
    const int k0 = blockIdx.x * 32;
    const int c0 = blockIdx.y * 32;

#pragma unroll
    for (int j = 0; j < 4; j++) {
        int c = c0 + ty + 8 * j;
        s[ty + 8 * j][tx] = Wc[(64 + c) * CIN + k0 + tx] * (1.0f / 64.0f);
    }
    __syncthreads();
#pragma unroll
    for (int j = 0; j < 4; j++) {
        int k = k0 + ty + 8 * j;
        g_WcT[k * COUT + c0 + tx] = s[tx][ty + 8 * j];
    }
}

// ---------------------------------------------------------------------------
// Kernel 1: GEMM, R8 mainloop + in-block split-K over 2 warp-groups.
// 256 threads: half 0 (tid 0-127) does k[0,128), half 1 does k[128,256).
// Each half: block tile 64c x 64p, thread tile 4 cpair x 4 pos, FFMA2,
// KC=32 double-buffered with per-half smem. Reduction via smem at the end.
// ---------------------------------------------------------------------------
__global__ __launch_bounds__(256)
void lss_gemm_kernel(const float* __restrict__ feat,
                     const float* __restrict__ bc)
{
    __shared__ float Ws[2][2][KC * CB];   // [half][buf][k][c] 32KB
    __shared__ float Fs[2][2][KC * PB];   // [half][buf][k][p] 32KB

    const int tid   = threadIdx.x;
    const int half  = tid >> 7;       // 0 or 1
    const int ltid  = tid & 127;
    const int kbase = half * KSPL;

    const int p0    = blockIdx.x * PB;
    const int b     = p0 / HW;
    const int hw0   = p0 - b * HW;
    const int cbase = blockIdx.y * CB;          // 0 or 64

    const float4* WcT4  = (const float4*)g_WcT;                               // row stride 32 f4
    const float4* feat4 = (const float4*)(feat + (size_t)b * CIN * HW + hw0); // row stride 704 f4

    const int lkk = ltid >> 4;        // 0..7
    const int lcv = ltid & 15;        // 0..15

    float4 wreg[4], freg[4];

    // prologue: chunk 0 of this half
#pragma unroll
    for (int it = 0; it < 4; it++) {
        int kg = kbase + lkk + it * 8;
        wreg[it] = WcT4[(size_t)kg * 32 + (cbase >> 2) + lcv];
        freg[it] = feat4[(size_t)kg * 704 + lcv];
    }
#pragma unroll
    for (int it = 0; it < 4; it++) {
        int kk = lkk + it * 8;
        ((float4*)Ws[half][0])[kk * 16 + lcv] = wreg[it];
        ((float4*)Fs[half][0])[kk * 16 + lcv] = freg[it];
    }
    __syncthreads();

    const int cy = (ltid >> 4) << 3;   // channel base 0..56 (4 pairs)
    const int px = (ltid & 15) << 2;   // position base 0..60

    unsigned long long acc[4][4];      // [cpair][pos]
#pragma unroll
    for (int i = 0; i < 4; i++)
#pragma unroll
        for (int j = 0; j < 4; j++) acc[i][j] = 0ull;

    int buf = 0;
    for (int ch = 0; ch < KSPL / KC; ch++) {     // 4 chunks per half
        if (ch < KSPL / KC - 1) {
            int k0 = kbase + (ch + 1) * KC;
#pragma unroll
            for (int it = 0; it < 4; it++) {
                int kg = k0 + lkk + it * 8;
                wreg[it] = WcT4[(size_t)kg * 32 + (cbase >> 2) + lcv];
                freg[it] = feat4[(size_t)kg * 704 + lcv];
            }
        }

        const float* Wsb = Ws[half][buf] + cy;
        const float* Fsb = Fs[half][buf] + px;
#pragma unroll 16
        for (int k = 0; k < KC; k++) {
            ulonglong2 w01 = *(const ulonglong2*)(Wsb + k * CB);       // pairs (c0,c1),(c2,c3)
            ulonglong2 w23 = *(const ulonglong2*)(Wsb + k * CB + 4);   // pairs (c4,c5),(c6,c7)
            float4 f = *(const float4*)(Fsb + k * PB);
            unsigned long long f0 = pk2(f.x), f1 = pk2(f.y),
                               f2 = pk2(f.z), f3 = pk2(f.w);
            ffma2(acc[0][0], w01.x, f0); ffma2(acc[0][1], w01.x, f1);
            ffma2(acc[0][2], w01.x, f2); ffma2(acc[0][3], w01.x, f3);
            ffma2(acc[1][0], w01.y, f0); ffma2(acc[1][1], w01.y, f1);
            ffma2(acc[1][2], w01.y, f2); ffma2(acc[1][3], w01.y, f3);
            ffma2(acc[2][0], w23.x, f0); ffma2(acc[2][1], w23.x, f1);
            ffma2(acc[2][2], w23.x, f2); ffma2(acc[2][3], w23.x, f3);
            ffma2(acc[3][0], w23.y, f0); ffma2(acc[3][1], w23.y, f1);
            ffma2(acc[3][2], w23.y, f2); ffma2(acc[3][3], w23.y, f3);
        }

        if (ch < KSPL / KC - 1) {
            int nb = buf ^ 1;
#pragma unroll
            for (int it = 0; it < 4; it++) {
                int kk = lkk + it * 8;
                ((float4*)Ws[half][nb])[kk * 16 + lcv] = wreg[it];
                ((float4*)Fs[half][nb])[kk * 16 + lcv] = freg[it];
            }
            __syncthreads();
            buf = nb;
        }
    }

    // ---- cross-half reduction: half 1 -> smem -> half 0 adds & stores ----
    __syncthreads();                               // mainloop smem reads done
    unsigned long long* red = (unsigned long long*)&Ws[0][0][0];   // 16KB region
    if (half == 1) {
#pragma unroll
        for (int i = 0; i < 4; i++)
#pragma unroll
            for (int j = 0; j < 4; j++)
                red[(i * 4 + j) * 128 + ltid] = acc[i][j];
    }
    __syncthreads();

    if (half == 0) {
        const float inv64 = 1.0f / 64.0f;
#pragma unroll
        for (int j = 0; j < 4; j++) {
            int c0 = cbase + cy + 2 * j;
            float b0 = bc[64 + c0] * inv64;
            float b1 = bc[64 + c0 + 1] * inv64;
            float2 v[4];
#pragma unroll
            for (int p = 0; p < 4; p++) {
                float2 a = upk(acc[j][p]);
                float2 q = upk(red[(j * 4 + p) * 128 + ltid]);
                v[p].x = a.x + q.x;
                v[p].y = a.y + q.y;
            }
            float4 r0 = make_float4(v[0].x + b0, v[1].x + b0, v[2].x + b0, v[3].x + b0);
            float4 r1 = make_float4(v[0].y + b1, v[1].y + b1, v[2].y + b1, v[3].y + b1);
            *(float4*)&g_ctx[((size_t)(b * COUT + c0)) * HW + hw0 + px]     = r0;
            *(float4*)&g_ctx[((size_t)(b * COUT + c0 + 1)) * HW + hw0 + px] = r1;
        }
    }
}

// ---------------------------------------------------------------------------
// Kernel 2: separable bilinear upsample (R7/R8 proven version, unchanged).
// ---------------------------------------------------------------------------
__global__ __launch_bounds__(256)
void lss_upsample_kernel(float* __restrict__ out)
{
    __shared__ float raw[SROWS][WW];
    __shared__ float hrow[SROWS][OUTW];
    __shared__ float ywy[YTILE];
    __shared__ int   yi0s[YTILE];

    const int tid   = threadIdx.x;
    const int t     = blockIdx.x;      // 0..7
    const int plane = blockIdx.y;      // 0..511

    const float SY = 32.0f / 432.0f;
    const float OY = 16.0f / 432.0f - 0.5f;
    const float SX = 88.0f / 496.0f;
    const float OX = 44.0f / 496.0f - 0.5f;

    const int rbase = max(4 * t - 1, 0);

    if (tid < YTILE) {
        int Y = t * YTILE + tid;
        float fy = fminf(fmaxf((float)Y * SY + OY, 0.0f), 31.0f);
        int   y0 = (int)fy;
        ywy[tid]  = fy - (float)y0;
        yi0s[tid] = y0 - rbase;        // 0..4, monotone non-decreasing
    }

    // Phase A: load 6 source rows (edge-clamped)
    const float* cb = g_ctx + (size_t)plane * HW;
    for (int i = tid; i < SROWS * WW; i += 256) {
        int r = i / WW, x = i - r * WW;
        int ry = min(rbase + r, HH - 1);
        raw[r][x] = cb[ry * WW + x];
    }
    __syncthreads();

    // Phase B: horizontal interpolation
    for (int i = tid; i < SROWS * 512; i += 256) {
        int r = i >> 9, X = i & 511;
        if (X < OUTW) {
            float fx = fminf(fmaxf((float)X * SX + OX, 0.0f), 87.0f);
            int   x0 = (int)fx;
            float wx = fx - (float)x0;
            int   x1 = min(x0 + 1, WW - 1);
            float a = raw[r][x0];
            hrow[r][X] = fmaf(wx, raw[r][x1] - a, a);
        }
    }
    __syncthreads();

    // Phase C: vertical pass. Two 124-thread halves each cover 27 rows.
    const int half = tid >> 7;         // 0 or 1
    const int lx   = tid & 127;        // x-column within half
    if (lx < XVEC) {
        const int xo    = lx << 2;
        const int ybeg  = half * YHALF;
        const int yend  = ybeg + YHALF;
        float4* orow = (float4*)out + (size_t)plane * OUTH * XVEC
                       + (size_t)(t * YTILE + ybeg) * XVEC + lx;
        int yy = ybeg;
        const int r0 = yi0s[ybeg];
#pragma unroll
        for (int r = 0; r < 5; r++) {
            if (r >= r0 && yy < yend && yi0s[yy] == r) {
                float4 a = *(const float4*)&hrow[r][xo];
                float4 b = *(const float4*)&hrow[r + 1][xo];
                float4 d;
                d.x = b.x - a.x; d.y = b.y - a.y; d.z = b.z - a.z; d.w = b.w - a.w;
                do {
                    float wy = ywy[yy];
                    float4 o;
                    o.x = fmaf(wy, d.x, a.x);
                    o.y = fmaf(wy, d.y, a.y);
                    o.z = fmaf(wy, d.z, a.z);
                    o.w = fmaf(wy, d.w, a.w);
                    __stcs(orow, o);
                    orow += XVEC;
                    yy++;
                } while (yy < yend && yi0s[yy] == r);
            }
        }
    }
}

extern "C" void kernel_launch(void* const* d_in, const int* in_sizes, int n_in,
                              void* d_out, int out_size)
{
    const float* feat = (const float*)d_in[0];
    const float* Wc   = (const float*)d_in[1];
    const float* bc   = (const float*)d_in[2];
    float* out        = (float*)d_out;

    dim3 pgrid(CIN / 32, COUT / 32);
    lss_prep_kernel<<<pgrid, 256>>>(Wc);

    dim3 ggrid(PTOT / PB, 2);
    lss_gemm_kernel<<<ggrid, 256>>>(feat, bc);

    dim3 ugrid(NYT, NPLANE);
    lss_upsample_kernel<<<ugrid, 256>>>(out);
}

// round 13
// speedup vs baseline: 1.6650x; 1.1021x over previous
#include <cuda_runtime.h>
#include <cuda_bf16.h>
#include <cstdint>

#define B_      4
#define CIN     256
#define HH      32
#define WW      88
#define HW      2816
#define PTOT    11264
#define COUT    128
#define OUTH    432
#define OUTW    496
#define XVEC    124             // 496/4
#define NPLANE  512
#define YTILE   54              // 432 = 8*54
#define NYT     8
#define SROWS   6
#define YHALF   27

#define KC      32              // k-chunk
#define PB      64              // positions per block
#define CB      64              // channels per block
#define KPAD    40              // bf16 per W smem row (80B, conflict-free ldsm)
#define PPAD    72              // bf16 per F smem row (144B, conflict-free ldsm)

__device__ float g_ctx[NPLANE * HW];
// W in bf16 hi/lo, scaled by 1/64, chunk-major: [kchunk][c][32]
__device__ __align__(16) __nv_bfloat16 g_Whi[CIN * COUT];
__device__ __align__(16) __nv_bfloat16 g_Wlo[CIN * COUT];

// ---------------------------------------------------------------------------
// mma / ldmatrix helpers
// ---------------------------------------------------------------------------
__device__ __forceinline__ void ldsm4(uint32_t* r, uint32_t a) {
    asm volatile("ldmatrix.sync.aligned.m8n8.x4.shared.b16 {%0,%1,%2,%3}, [%4];"
        : "=r"(r[0]), "=r"(r[1]), "=r"(r[2]), "=r"(r[3]) : "r"(a));
}
__device__ __forceinline__ void ldsm4t(uint32_t* r, uint32_t a) {
    asm volatile("ldmatrix.sync.aligned.m8n8.x4.trans.shared.b16 {%0,%1,%2,%3}, [%4];"
        : "=r"(r[0]), "=r"(r[1]), "=r"(r[2]), "=r"(r[3]) : "r"(a));
}
__device__ __forceinline__ void mma_bf16(float* d, const uint32_t* a,
                                         uint32_t b0, uint32_t b1) {
    asm volatile("mma.sync.aligned.m16n8k16.row.col.f32.bf16.bf16.f32 "
        "{%0,%1,%2,%3}, {%4,%5,%6,%7}, {%8,%9}, {%0,%1,%2,%3};"
        : "+f"(d[0]), "+f"(d[1]), "+f"(d[2]), "+f"(d[3])
        : "r"(a[0]), "r"(a[1]), "r"(a[2]), "r"(a[3]), "r"(b0), "r"(b1));
}

// ---------------------------------------------------------------------------
// Kernel 0: W -> bf16 hi/lo, scaled 1/64, chunk-major [k>>5][c][k&31]
// ---------------------------------------------------------------------------
__global__ __launch_bounds__(256)
void lss_prep_kernel(const float* __restrict__ Wc)
{
    int i = blockIdx.x * 256 + threadIdx.x;   // 32768 = 128c * 256k
    int c = i >> 8, k = i & 255;
    float w = Wc[(64 + c) * CIN + k] * (1.0f / 64.0f);
    __nv_bfloat16 hi = __float2bfloat16_rn(w);
    float r = w - __bfloat162float(hi);
    __nv_bfloat16 lo = __float2bfloat16_rn(r);
    int o = (k >> 5) * (COUT * 32) + c * 32 + (k & 31);
    g_Whi[o] = hi;
    g_Wlo[o] = lo;
}

// ---------------------------------------------------------------------------
// Kernel 1: split-bf16 tensor-core GEMM.
// Block 64c x 64p, 128 threads (4 warps). Warp w: m-tile = channels w*16..+15,
// 8 n8-tiles over 64 positions. KC=32 double-buffered (R8 loader skeleton).
// acc += Ahi*Bhi + Ahi*Blo + Alo*Bhi  (fp32 accum).
// ---------------------------------------------------------------------------
__global__ __launch_bounds__(128)
void lss_gemm_kernel(const float* __restrict__ feat,
                     const float* __restrict__ bc)
{
    __shared__ __align__(16) __nv_bfloat16 Whi[2][CB * KPAD];
    __shared__ __align__(16) __nv_bfloat16 Wlo[2][CB * KPAD];
    __shared__ __align__(16) __nv_bfloat16 Fhi[2][KC * PPAD];
    __shared__ __align__(16) __nv_bfloat16 Flo[2][KC * PPAD];

    const int tid   = threadIdx.x;
    const int p0    = blockIdx.x * PB;
    const int b     = p0 / HW;
    const int hw0   = p0 - b * HW;
    const int cbase = blockIdx.y * CB;          // 0 or 64

    const float4* feat4 = (const float4*)(feat + (size_t)b * CIN * HW + hw0); // row stride 704 f4
    const uint4*  WhiG  = (const uint4*)g_Whi;
    const uint4*  WloG  = (const uint4*)g_Wlo;

    const int lkk = tid >> 4;        // 0..7
    const int lcv = tid & 15;        // 0..15

    uint4 whr[2], wlr[2];
    float4 fr[4];

    auto load_regs = [&](int ch) {
        int sb = ch * 512 + cbase * 4;          // uint4 index of W slab
        whr[0] = WhiG[sb + tid];       whr[1] = WhiG[sb + tid + 128];
        wlr[0] = WloG[sb + tid];       wlr[1] = WloG[sb + tid + 128];
#pragma unroll
        for (int it = 0; it < 4; it++)
            fr[it] = feat4[(size_t)(ch * KC + lkk + it * 8) * 704 + lcv];
    };

    auto store_chunk = [&](int buf) {
#pragma unroll
        for (int j = 0; j < 2; j++) {
            int i = tid + j * 128;
            int c = i >> 2, kq = i & 3;
            *(uint4*)((char*)Whi[buf] + c * (KPAD * 2) + kq * 16) = whr[j];
            *(uint4*)((char*)Wlo[buf] + c * (KPAD * 2) + kq * 16) = wlr[j];
        }
#pragma unroll
        for (int it = 0; it < 4; it++) {
            int k = lkk + it * 8;
            float4 f = fr[it];
            __nv_bfloat162 h01, h23, l01, l23;
            h01.x = __float2bfloat16_rn(f.x); h01.y = __float2bfloat16_rn(f.y);
            h23.x = __float2bfloat16_rn(f.z); h23.y = __float2bfloat16_rn(f.w);
            l01.x = __float2bfloat16_rn(f.x - __bfloat162float(h01.x));
            l01.y = __float2bfloat16_rn(f.y - __bfloat162float(h01.y));
            l23.x = __float2bfloat16_rn(f.z - __bfloat162float(h23.x));
            l23.y = __float2bfloat16_rn(f.w - __bfloat162float(h23.y));
            uint2 hv, lv;
            hv.x = *(uint32_t*)&h01; hv.y = *(uint32_t*)&h23;
            lv.x = *(uint32_t*)&l01; lv.y = *(uint32_t*)&l23;
            int base = k * PPAD + 4 * lcv;      // bf16 units, 8B aligned
            *(uint2*)&Fhi[buf][base] = hv;
            *(uint2*)&Flo[buf][base] = lv;
        }
    };

    load_regs(0);
    store_chunk(0);
    __syncthreads();

    const int wid  = tid >> 5;
    const int lane = tid & 31;
    const int c0w  = wid * 16;

    float acc[8][4];
#pragma unroll
    for (int i = 0; i < 8; i++)
#pragma unroll
        for (int j = 0; j < 4; j++) acc[i][j] = 0.0f;

    // per-lane ldmatrix row/col components (constant across chunks)
    const int a_row = c0w + (lane & 15);
    const int a_coff = (lane >> 4) << 3;                  // 0 or 8
    const int b_krow = (lane & 7) + (((lane >> 3) & 1) << 3);   // 0..15
    const int b_coff = (lane >> 4) << 3;                  // 0 or 8

    uint32_t whiB[2], wloB[2], fhiB[2], floB[2];
#pragma unroll
    for (int s = 0; s < 2; s++) {
        whiB[s] = (uint32_t)__cvta_generic_to_shared(Whi[s]);
        wloB[s] = (uint32_t)__cvta_generic_to_shared(Wlo[s]);
        fhiB[s] = (uint32_t)__cvta_generic_to_shared(Fhi[s]);
        floB[s] = (uint32_t)__cvta_generic_to_shared(Flo[s]);
    }

    int buf = 0;
    for (int ch = 0; ch < CIN / KC; ch++) {
        if (ch < CIN / KC - 1) load_regs(ch + 1);

#pragma unroll
        for (int ks = 0; ks < KC; ks += 16) {
            uint32_t ahi[4], alo[4];
            uint32_t aoff = (uint32_t)(a_row * KPAD + ks + a_coff) * 2;
            ldsm4(ahi, whiB[buf] + aoff);
            ldsm4(alo, wloB[buf] + aoff);
#pragma unroll
            for (int nt2 = 0; nt2 < 4; nt2++) {
                uint32_t bhi[4], blo[4];
                uint32_t boff = (uint32_t)((ks + b_krow) * PPAD + nt2 * 16 + b_coff) * 2;
                ldsm4t(bhi, fhiB[buf] + boff);
                ldsm4t(blo, floB[buf] + boff);
                int nt = nt2 * 2;
                mma_bf16(acc[nt],     ahi, bhi[0], bhi[1]);
                mma_bf16(acc[nt],     ahi, blo[0], blo[1]);
                mma_bf16(acc[nt],     alo, bhi[0], bhi[1]);
                mma_bf16(acc[nt + 1], ahi, bhi[2], bhi[3]);
                mma_bf16(acc[nt + 1], ahi, blo[2], blo[3]);
                mma_bf16(acc[nt + 1], alo, bhi[2], bhi[3]);
            }
        }

        if (ch < CIN / KC - 1) {
            store_chunk(buf ^ 1);
            __syncthreads();
            buf ^= 1;
        }
    }

    // Epilogue: D[m][n] lane map: d0:(m=lane>>2, n=2*(lane&3)), d1:n+1,
    // d2:(m+8,n), d3:(m+8,n+1).
    const float inv64 = 1.0f / 64.0f;
    const int m0 = cbase + c0w + (lane >> 2);
    const int pb2 = 2 * (lane & 3);
    const float bia0 = bc[64 + m0] * inv64;
    const float bia1 = bc[64 + m0 + 8] * inv64;
    float* row0 = &g_ctx[((size_t)(b * COUT + m0)) * HW + hw0 + pb2];
    float* row1 = &g_ctx[((size_t)(b * COUT + m0 + 8)) * HW + hw0 + pb2];
#pragma unroll
    for (int nt = 0; nt < 8; nt++) {
        float2 v0 = make_float2(acc[nt][0] + bia0, acc[nt][1] + bia0);
        float2 v1 = make_float2(acc[nt][2] + bia1, acc[nt][3] + bia1);
        *(float2*)(row0 + nt * 8) = v0;
        *(float2*)(row1 + nt * 8) = v1;
    }
}

// ---------------------------------------------------------------------------
// Kernel 2: separable bilinear upsample (R7/R8 proven version, unchanged).
// ---------------------------------------------------------------------------
__global__ __launch_bounds__(256)
void lss_upsample_kernel(float* __restrict__ out)
{
    __shared__ float raw[SROWS][WW];
    __shared__ float hrow[SROWS][OUTW];
    __shared__ float ywy[YTILE];
    __shared__ int   yi0s[YTILE];

    const int tid   = threadIdx.x;
    const int t     = blockIdx.x;      // 0..7
    const int plane = blockIdx.y;      // 0..511

    const float SY = 32.0f / 432.0f;
    const float OY = 16.0f / 432.0f - 0.5f;
    const float SX = 88.0f / 496.0f;
    const float OX = 44.0f / 496.0f - 0.5f;

    const int rbase = max(4 * t - 1, 0);

    if (tid < YTILE) {
        int Y = t * YTILE + tid;
        float fy = fminf(fmaxf((float)Y * SY + OY, 0.0f), 31.0f);
        int   y0 = (int)fy;
        ywy[tid]  = fy - (float)y0;
        yi0s[tid] = y0 - rbase;        // 0..4, monotone non-decreasing
    }

    // Phase A: load 6 source rows (edge-clamped)
    const float* cb = g_ctx + (size_t)plane * HW;
    for (int i = tid; i < SROWS * WW; i += 256) {
        int r = i / WW, x = i - r * WW;
        int ry = min(rbase + r, HH - 1);
        raw[r][x] = cb[ry * WW + x];
    }
    __syncthreads();

    // Phase B: horizontal interpolation
    for (int i = tid; i < SROWS * 512; i += 256) {
        int r = i >> 9, X = i & 511;
        if (X < OUTW) {
            float fx = fminf(fmaxf((float)X * SX + OX, 0.0f), 87.0f);
            int   x0 = (int)fx;
            float wx = fx - (float)x0;
            int   x1 = min(x0 + 1, WW - 1);
            float a = raw[r][x0];
            hrow[r][X] = fmaf(wx, raw[r][x1] - a, a);
        }
    }
    __syncthreads();

    // Phase C: vertical pass. Two 124-thread halves each cover 27 rows.
    const int half = tid >> 7;         // 0 or 1
    const int lx   = tid & 127;        // x-column within half
    if (lx < XVEC) {
        const int xo    = lx << 2;
        const int ybeg  = half * YHALF;
        const int yend  = ybeg + YHALF;
        float4* orow = (float4*)out + (size_t)plane * OUTH * XVEC
                       + (size_t)(t * YTILE + ybeg) * XVEC + lx;
        int yy = ybeg;
        const int r0 = yi0s[ybeg];
#pragma unroll
        for (int r = 0; r < 5; r++) {
            if (r >= r0 && yy < yend && yi0s[yy] == r) {
                float4 a = *(const float4*)&hrow[r][xo];
                float4 b = *(const float4*)&hrow[r + 1][xo];
                float4 d;
                d.x = b.x - a.x; d.y = b.y - a.y; d.z = b.z - a.z; d.w = b.w - a.w;
                do {
                    float wy = ywy[yy];
                    float4 o;
                    o.x = fmaf(wy, d.x, a.x);
                    o.y = fmaf(wy, d.y, a.y);
                    o.z = fmaf(wy, d.z, a.z);
                    o.w = fmaf(wy, d.w, a.w);
                    __stcs(orow, o);
                    orow += XVEC;
                    yy++;
                } while (yy < yend && yi0s[yy] == r);
            }
        }
    }
}

extern "C" void kernel_launch(void* const* d_in, const int* in_sizes, int n_in,
                              void* d_out, int out_size)
{
    const float* feat = (const float*)d_in[0];
    const float* Wc   = (const float*)d_in[1];
    const float* bc   = (const float*)d_in[2];
    float* out        = (float*)d_out;

    lss_prep_kernel<<<128, 256>>>(Wc);

    dim3 ggrid(PTOT / PB, 2);
    lss_gemm_kernel<<<ggrid, 128>>>(feat, bc);

    dim3 ugrid(NYT, NPLANE);
    lss_upsample_kernel<<<ugrid, 256>>>(out);
}

// round 14
// speedup vs baseline: 1.7024x; 1.0225x over previous
#include <cuda_runtime.h>
#include <cuda_bf16.h>
#include <cstdint>

#define B_      4
#define CIN     256
#define HH      32
#define WW      88
#define HW      2816
#define PTOT    11264
#define COUT    128
#define OUTH    432
#define OUTW    496
#define XVEC    124             // 496/4
#define NPLANE  512
#define YTILE   54              // 432 = 8*54
#define NYT     8
#define SROWS   6
#define YHALF   27

#define KC      32              // k-chunk
#define PB      64              // positions per block
#define CB      64              // channels per block
#define KPAD    40              // bf16 per W smem row (80B, conflict-free ldsm)
#define PPAD    72              // bf16 per F smem row (144B, conflict-free ldsm)

__device__ float g_ctx[NPLANE * HW];

// ---------------------------------------------------------------------------
// mma / ldmatrix helpers
// ---------------------------------------------------------------------------
__device__ __forceinline__ void ldsm4(uint32_t* r, uint32_t a) {
    asm volatile("ldmatrix.sync.aligned.m8n8.x4.shared.b16 {%0,%1,%2,%3}, [%4];"
        : "=r"(r[0]), "=r"(r[1]), "=r"(r[2]), "=r"(r[3]) : "r"(a));
}
__device__ __forceinline__ void ldsm4t(uint32_t* r, uint32_t a) {
    asm volatile("ldmatrix.sync.aligned.m8n8.x4.trans.shared.b16 {%0,%1,%2,%3}, [%4];"
        : "=r"(r[0]), "=r"(r[1]), "=r"(r[2]), "=r"(r[3]) : "r"(a));
}
__device__ __forceinline__ void mma_bf16(float* d, const uint32_t* a,
                                         uint32_t b0, uint32_t b1) {
    asm volatile("mma.sync.aligned.m16n8k16.row.col.f32.bf16.bf16.f32 "
        "{%0,%1,%2,%3}, {%4,%5,%6,%7}, {%8,%9}, {%0,%1,%2,%3};"
        : "+f"(d[0]), "+f"(d[1]), "+f"(d[2]), "+f"(d[3])
        : "r"(a[0]), "r"(a[1]), "r"(a[2]), "r"(a[3]), "r"(b0), "r"(b1));
}

// split a float into bf16 hi + bf16 lo (residual)
__device__ __forceinline__ void bsplit(float v, __nv_bfloat16& hi, __nv_bfloat16& lo) {
    hi = __float2bfloat16_rn(v);
    lo = __float2bfloat16_rn(v - __bfloat162float(hi));
}

// ---------------------------------------------------------------------------
// Kernel 1: split-bf16 tensor-core GEMM, W converted in the loader
// (Wc is [c][k] row-major = exactly the A-operand layout; no transpose).
// Block 64c x 64p, 128 threads (4 warps). Warp w: m-tile = channels w*16..+15,
// 8 n8-tiles over 64 positions. KC=32 double-buffered.
// acc += Ahi*Bhi + Ahi*Blo + Alo*Bhi  (fp32 accum).
// ---------------------------------------------------------------------------
__global__ __launch_bounds__(128)
void lss_gemm_kernel(const float* __restrict__ feat,
                     const float* __restrict__ Wc,
                     const float* __restrict__ bc)
{
    __shared__ __align__(16) __nv_bfloat16 Whi[2][CB * KPAD];
    __shared__ __align__(16) __nv_bfloat16 Wlo[2][CB * KPAD];
    __shared__ __align__(16) __nv_bfloat16 Fhi[2][KC * PPAD];
    __shared__ __align__(16) __nv_bfloat16 Flo[2][KC * PPAD];

    const int tid   = threadIdx.x;
    const int p0    = blockIdx.x * PB;
    const int b     = p0 / HW;
    const int hw0   = p0 - b * HW;
    const int cbase = blockIdx.y * CB;          // 0 or 64

    const float4* feat4 = (const float4*)(feat + (size_t)b * CIN * HW + hw0); // row stride 704 f4

    // F loader mapping (proven)
    const int lkk = tid >> 4;        // 0..7
    const int lcv = tid & 15;        // 0..15

    // W loader mapping: 4 passes, each pass 16 c-rows x 8 k-quads
    const int wcc = tid >> 3;        // 0..15  (c within pass)
    const int wkq = tid & 7;         // 0..7   (k float4-quad)
    const float* Wbase = Wc + (size_t)(64 + cbase + wcc) * CIN + wkq * 4;

    float4 wf[4], fr[4];

    auto load_regs = [&](int ch) {
        int k0 = ch * KC;
#pragma unroll
        for (int j = 0; j < 4; j++)
            wf[j] = *(const float4*)(Wbase + (size_t)(16 * j) * CIN + k0);
#pragma unroll
        for (int it = 0; it < 4; it++)
            fr[it] = feat4[(size_t)(k0 + lkk + it * 8) * 704 + lcv];
    };

    const float inv64 = 1.0f / 64.0f;

    auto store_chunk = [&](int buf) {
#pragma unroll
        for (int j = 0; j < 4; j++) {
            int cloc = wcc + 16 * j;
            __nv_bfloat162 h01, h23, l01, l23;
            bsplit(wf[j].x * inv64, h01.x, l01.x);
            bsplit(wf[j].y * inv64, h01.y, l01.y);
            bsplit(wf[j].z * inv64, h23.x, l23.x);
            bsplit(wf[j].w * inv64, h23.y, l23.y);
            uint2 hv, lv;
            hv.x = *(uint32_t*)&h01; hv.y = *(uint32_t*)&h23;
            lv.x = *(uint32_t*)&l01; lv.y = *(uint32_t*)&l23;
            int base = cloc * KPAD + wkq * 4;     // bf16 units, 8B aligned
            *(uint2*)&Whi[buf][base] = hv;
            *(uint2*)&Wlo[buf][base] = lv;
        }
#pragma unroll
        for (int it = 0; it < 4; it++) {
            int k = lkk + it * 8;
            float4 f = fr[it];
            __nv_bfloat162 h01, h23, l01, l23;
            bsplit(f.x, h01.x, l01.x);
            bsplit(f.y, h01.y, l01.y);
            bsplit(f.z, h23.x, l23.x);
            bsplit(f.w, h23.y, l23.y);
            uint2 hv, lv;
            hv.x = *(uint32_t*)&h01; hv.y = *(uint32_t*)&h23;
            lv.x = *(uint32_t*)&l01; lv.y = *(uint32_t*)&l23;
            int base = k * PPAD + 4 * lcv;        // bf16 units, 8B aligned
            *(uint2*)&Fhi[buf][base] = hv;
            *(uint2*)&Flo[buf][base] = lv;
        }
    };

    load_regs(0);
    store_chunk(0);
    __syncthreads();

    const int wid  = tid >> 5;
    const int lane = tid & 31;
    const int c0w  = wid * 16;

    float acc[8][4];
#pragma unroll
    for (int i = 0; i < 8; i++)
#pragma unroll
        for (int j = 0; j < 4; j++) acc[i][j] = 0.0f;

    // per-lane ldmatrix row/col components (constant across chunks)
    const int a_row = c0w + (lane & 15);
    const int a_coff = (lane >> 4) << 3;                        // 0 or 8
    const int b_krow = (lane & 7) + (((lane >> 3) & 1) << 3);   // 0..15
    const int b_coff = (lane >> 4) << 3;                        // 0 or 8

    uint32_t whiB[2], wloB[2], fhiB[2], floB[2];
#pragma unroll
    for (int s = 0; s < 2; s++) {
        whiB[s] = (uint32_t)__cvta_generic_to_shared(Whi[s]);
        wloB[s] = (uint32_t)__cvta_generic_to_shared(Wlo[s]);
        fhiB[s] = (uint32_t)__cvta_generic_to_shared(Fhi[s]);
        floB[s] = (uint32_t)__cvta_generic_to_shared(Flo[s]);
    }

    int buf = 0;
    for (int ch = 0; ch < CIN / KC; ch++) {
        if (ch < CIN / KC - 1) load_regs(ch + 1);

#pragma unroll
        for (int ks = 0; ks < KC; ks += 16) {
            uint32_t ahi[4], alo[4];
            uint32_t aoff = (uint32_t)(a_row * KPAD + ks + a_coff) * 2;
            ldsm4(ahi, whiB[buf] + aoff);
            ldsm4(alo, wloB[buf] + aoff);
#pragma unroll
            for (int nt2 = 0; nt2 < 4; nt2++) {
                uint32_t bhi[4], blo[4];
                uint32_t boff = (uint32_t)((ks + b_krow) * PPAD + nt2 * 16 + b_coff) * 2;
                ldsm4t(bhi, fhiB[buf] + boff);
                ldsm4t(blo, floB[buf] + boff);
                int nt = nt2 * 2;
                mma_bf16(acc[nt],     ahi, bhi[0], bhi[1]);
                mma_bf16(acc[nt],     ahi, blo[0], blo[1]);
                mma_bf16(acc[nt],     alo, bhi[0], bhi[1]);
                mma_bf16(acc[nt + 1], ahi, bhi[2], bhi[3]);
                mma_bf16(acc[nt + 1], ahi, blo[2], blo[3]);
                mma_bf16(acc[nt + 1], alo, bhi[2], bhi[3]);
            }
        }

        if (ch < CIN / KC - 1) {
            store_chunk(buf ^ 1);
            __syncthreads();
            buf ^= 1;
        }
    }

    // Epilogue: D[m][n] lane map: d0:(m=lane>>2, n=2*(lane&3)), d1:n+1,
    // d2:(m+8,n), d3:(m+8,n+1).
    const int m0 = cbase + c0w + (lane >> 2);
    const int pb2 = 2 * (lane & 3);
    const float bia0 = bc[64 + m0] * inv64;
    const float bia1 = bc[64 + m0 + 8] * inv64;
    float* row0 = &g_ctx[((size_t)(b * COUT + m0)) * HW + hw0 + pb2];
    float* row1 = &g_ctx[((size_t)(b * COUT + m0 + 8)) * HW + hw0 + pb2];
#pragma unroll
    for (int nt = 0; nt < 8; nt++) {
        float2 v0 = make_float2(acc[nt][0] + bia0, acc[nt][1] + bia0);
        float2 v1 = make_float2(acc[nt][2] + bia1, acc[nt][3] + bia1);
        *(float2*)(row0 + nt * 8) = v0;
        *(float2*)(row1 + nt * 8) = v1;
    }
}

// ---------------------------------------------------------------------------
// Kernel 2: separable bilinear upsample (proven version, unchanged).
// ---------------------------------------------------------------------------
__global__ __launch_bounds__(256)
void lss_upsample_kernel(float* __restrict__ out)
{
    __shared__ float raw[SROWS][WW];
    __shared__ float hrow[SROWS][OUTW];
    __shared__ float ywy[YTILE];
    __shared__ int   yi0s[YTILE];

    const int tid   = threadIdx.x;
    const int t     = blockIdx.x;      // 0..7
    const int plane = blockIdx.y;      // 0..511

    const float SY = 32.0f / 432.0f;
    const float OY = 16.0f / 432.0f - 0.5f;
    const float SX = 88.0f / 496.0f;
    const float OX = 44.0f / 496.0f - 0.5f;

    const int rbase = max(4 * t - 1, 0);

    if (tid < YTILE) {
        int Y = t * YTILE + tid;
        float fy = fminf(fmaxf((float)Y * SY + OY, 0.0f), 31.0f);
        int   y0 = (int)fy;
        ywy[tid]  = fy - (float)y0;
        yi0s[tid] = y0 - rbase;        // 0..4, monotone non-decreasing
    }

    // Phase A: load 6 source rows (edge-clamped)
    const float* cb = g_ctx + (size_t)plane * HW;
    for (int i = tid; i < SROWS * WW; i += 256) {
        int r = i / WW, x = i - r * WW;
        int ry = min(rbase + r, HH - 1);
        raw[r][x] = cb[ry * WW + x];
    }
    __syncthreads();

    // Phase B: horizontal interpolation
    for (int i = tid; i < SROWS * 512; i += 256) {
        int r = i >> 9, X = i & 511;
        if (X < OUTW) {
            float fx = fminf(fmaxf((float)X * SX + OX, 0.0f), 87.0f);
            int   x0 = (int)fx;
            float wx = fx - (float)x0;
            int   x1 = min(x0 + 1, WW - 1);
            float a = raw[r][x0];
            hrow[r][X] = fmaf(wx, raw[r][x1] - a, a);
        }
    }
    __syncthreads();

    // Phase C: vertical pass. Two 124-thread halves each cover 27 rows.
    const int half = tid >> 7;         // 0 or 1
    const int lx   = tid & 127;        // x-column within half
    if (lx < XVEC) {
        const int xo    = lx << 2;
        const int ybeg  = half * YHALF;
        const int yend  = ybeg + YHALF;
        float4* orow = (float4*)out + (size_t)plane * OUTH * XVEC
                       + (size_t)(t * YTILE + ybeg) * XVEC + lx;
        int yy = ybeg;
        const int r0 = yi0s[ybeg];
#pragma unroll
        for (int r = 0; r < 5; r++) {
            if (r >= r0 && yy < yend && yi0s[yy] == r) {
                float4 a = *(const float4*)&hrow[r][xo];
                float4 b = *(const float4*)&hrow[r + 1][xo];
                float4 d;
                d.x = b.x - a.x; d.y = b.y - a.y; d.z = b.z - a.z; d.w = b.w - a.w;
                do {
                    float wy = ywy[yy];
                    float4 o;
                    o.x = fmaf(wy, d.x, a.x);
                    o.y = fmaf(wy, d.y, a.y);
                    o.z = fmaf(wy, d.z, a.z);
                    o.w = fmaf(wy, d.w, a.w);
                    __stcs(orow, o);
                    orow += XVEC;
                    yy++;
                } while (yy < yend && yi0s[yy] == r);
            }
        }
    }
}

extern "C" void kernel_launch(void* const* d_in, const int* in_sizes, int n_in,
                              void* d_out, int out_size)
{
    const float* feat = (const float*)d_in[0];
    const float* Wc   = (const float*)d_in[1];
    const float* bc   = (const float*)d_in[2];
    float* out        = (float*)d_out;

    dim3 ggrid(PTOT / PB, 2);
    lss_gemm_kernel<<<ggrid, 128>>>(feat, Wc, bc);

    dim3 ugrid(NYT, NPLANE);
    lss_upsample_kernel<<<ugrid, 256>>>(out);
}